// round 15
// baseline (speedup 1.0000x reference)
#include <cuda_runtime.h>
#include <cuda_fp16.h>
#include <math.h>
#include <stdint.h>

// Problem constants
#define B_SZ   2
#define L_SZ   2048
#define D_SZ   1024
#define H_SZ   16
#define E3_SZ  3072
#define MTOK   (B_SZ * L_SZ)        // 4096
#define BH_SZ  32

#define NEG_INF __int_as_float(0xff800000)
#define EXPC 0.18033688f            // 0.125 * log2(e)

// Scratch (device globals; allocation is forbidden)
__device__ __half g_xh[(size_t)MTOK * D_SZ];          // fp16 x
__device__ __half g_wqkvh[(size_t)E3_SZ * D_SZ];      // fp16 qkv_w
__device__ __half g_wouth[(size_t)D_SZ * D_SZ];       // fp16 out_w
__device__ __half g_qkvh[(size_t)MTOK * E3_SZ];       // fp16 qkv
__device__ __half g_oh[(size_t)MTOK * D_SZ];          // fp16 O (pre out-proj)
__device__ float  g_phase[(size_t)BH_SZ * L_SZ];      // [bh, l]

// ---------------------------------------------------------------------------
// helpers
// ---------------------------------------------------------------------------
__device__ __forceinline__ uint32_t f2h2(float lo, float hi) {
    __half2 h = __floats2half2_rn(lo, hi);
    return *reinterpret_cast<uint32_t*>(&h);
}
__device__ __forceinline__ void mma_f16(float c[4], const uint32_t a[4],
                                        const uint32_t b[2]) {
    asm volatile(
        "mma.sync.aligned.m16n8k16.row.col.f32.f16.f16.f32 "
        "{%0,%1,%2,%3}, {%4,%5,%6,%7}, {%8,%9}, {%0,%1,%2,%3};"
        : "+f"(c[0]), "+f"(c[1]), "+f"(c[2]), "+f"(c[3])
        : "r"(a[0]), "r"(a[1]), "r"(a[2]), "r"(a[3]), "r"(b[0]), "r"(b[1]));
}
__device__ __forceinline__ void cp16(uint32_t dst, const void* src) {
    asm volatile("cp.async.cg.shared.global [%0], [%1], 16;"
                 :: "r"(dst), "l"(src) : "memory");
}
#define CP_COMMIT() asm volatile("cp.async.commit_group;" ::: "memory")

#define LDSM_X4(r0, r1, r2, r3, addr)                                        \
    asm volatile("ldmatrix.sync.aligned.m8n8.x4.shared.b16 "                 \
                 "{%0,%1,%2,%3}, [%4];"                                      \
                 : "=r"(r0), "=r"(r1), "=r"(r2), "=r"(r3) : "r"(addr))

// ---------------------------------------------------------------------------
// fp32 -> fp16 elementwise convert (vectorized x4)
// ---------------------------------------------------------------------------
__global__ void __launch_bounds__(256) f2h_kernel(
    const float4* __restrict__ src, uint2* __restrict__ dst, int n4)
{
    int i = blockIdx.x * 256 + threadIdx.x;
    if (i < n4) {
        float4 v = src[i];
        uint2 o = {f2h2(v.x, v.y), f2h2(v.z, v.w)};
        dst[i] = o;
    }
}

// ===========================================================================
// GEMM v2: C[M,N] = A[M,K] @ B[N,K]^T + bias[N]  (all-fp16 in, fp32 acc)
// CTA 128x128, 8 warps (4x2), warp tile 32x64, k-chunk 64, 3-stage ring,
// ldmatrix fragments, single sync per chunk. ~115 regs -> 2 CTAs/SM.
// stage s (words): A @ s*8192 (128x32w), B @ s*8192+4096 (128x32w)
// ===========================================================================
template<int OUTH>
__global__ void __launch_bounds__(256, 2) gemm_mma(
    const __half* __restrict__ A, const __half* __restrict__ Bm,
    const float* __restrict__ bias, void* __restrict__ Cv, int N, int K)
{
    extern __shared__ uint32_t sm[];
    const uint32_t smb = (uint32_t)__cvta_generic_to_shared(sm);
    const int tid = threadIdx.x, wid = tid >> 5, lane = tid & 31;
    const int gid = lane >> 2, tig = lane & 3;
    const int wy = wid >> 1, wx = wid & 1;
    const int tm = blockIdx.y * 128, tn = blockIdx.x * 128;

    const int ar = tid & 127, sel = tid >> 7;   // sel 0 -> A row, 1 -> B row
    const __half* rg = (sel ? Bm + (size_t)(tn + ar) * K
                            : A  + (size_t)(tm + ar) * K);

    const int mm = lane >> 3, rr = lane & 7;
    const int a_k = mm >> 1, a_r8 = (mm & 1) * 8;
    const int b_k = mm & 1,  b_n8 = (mm >> 1) * 8;
    uint32_t aoff[2], boff[4];
#pragma unroll
    for (int mi = 0; mi < 2; ++mi)
        aoff[mi] = (uint32_t)(((wy * 32 + mi * 16 + a_r8 + rr) * 32) << 2);
#pragma unroll
    for (int np = 0; np < 4; ++np)
        boff[np] = (uint32_t)((4096 + (wx * 64 + np * 16 + b_n8 + rr) * 32) << 2);

    float acc[2][8][4];
#pragma unroll
    for (int i = 0; i < 2; ++i)
#pragma unroll
        for (int j = 0; j < 8; ++j)
#pragma unroll
            for (int v = 0; v < 4; ++v) acc[i][j][v] = 0.f;

    const int T = K >> 6;

#define G_ISSUE(t, s) do {                                                   \
    const __half* _rp = rg + (t) * 64;                                       \
    uint32_t _rd = smb + (((s) * 8192 + sel * 4096 + ar * 32) << 2);         \
    _Pragma("unroll")                                                        \
    for (int cc = 0; cc < 8; ++cc)                                           \
        cp16(_rd + (((cc ^ (ar & 7)) << 2) << 2), _rp + cc * 8);             \
} while (0)

    G_ISSUE(0, 0);
    CP_COMMIT();
    if (T > 1) { G_ISSUE(1, 1); CP_COMMIT(); }

    for (int t = 0; t < T; ++t) {
        if (t + 1 < T) { asm volatile("cp.async.wait_group 1;" ::: "memory"); }
        else           { asm volatile("cp.async.wait_group 0;" ::: "memory"); }
        __syncthreads();
        const uint32_t sbase = smb + (((t % 3) * 8192) << 2);
#pragma unroll
        for (int j4 = 0; j4 < 4; ++j4) {
            uint32_t ax = (uint32_t)(((2 * j4 + a_k) ^ rr) << 4);
            uint32_t bx = (uint32_t)(((2 * j4 + b_k) ^ rr) << 4);
            uint32_t a[2][4], b2[8][2];
#pragma unroll
            for (int mi = 0; mi < 2; ++mi)
                LDSM_X4(a[mi][0], a[mi][1], a[mi][2], a[mi][3],
                        sbase + aoff[mi] + ax);
#pragma unroll
            for (int np = 0; np < 4; ++np)
                LDSM_X4(b2[2 * np][0], b2[2 * np][1],
                        b2[2 * np + 1][0], b2[2 * np + 1][1],
                        sbase + boff[np] + bx);
#pragma unroll
            for (int mi = 0; mi < 2; ++mi)
#pragma unroll
                for (int ni = 0; ni < 8; ++ni)
                    mma_f16(acc[mi][ni], a[mi], b2[ni]);
        }
        // no second sync: with a 3-stage ring the write target (t+2)%3 was
        // last read at iteration t-1, which every warp completed before the
        // top-of-loop barrier of iteration t.
        if (t + 2 < T) { G_ISSUE(t + 2, (t + 2) % 3); CP_COMMIT(); }
    }

#pragma unroll
    for (int mi = 0; mi < 2; ++mi) {
        int row = tm + wy * 32 + mi * 16 + gid;
#pragma unroll
        for (int ni = 0; ni < 8; ++ni) {
            int col = tn + wx * 64 + ni * 8 + tig * 2;
            float b0 = bias[col], b1 = bias[col + 1];
            if (OUTH) {
                __half* Ch = (__half*)Cv;
                *(uint32_t*)(Ch + (size_t)row * N + col) =
                    f2h2(acc[mi][ni][0] + b0, acc[mi][ni][1] + b1);
                *(uint32_t*)(Ch + (size_t)(row + 8) * N + col) =
                    f2h2(acc[mi][ni][2] + b0, acc[mi][ni][3] + b1);
            } else {
                float* Cf = (float*)Cv;
                float2 o0 = {acc[mi][ni][0] + b0, acc[mi][ni][1] + b1};
                float2 o1 = {acc[mi][ni][2] + b0, acc[mi][ni][3] + b1};
                *(float2*)(Cf + (size_t)row * N + col)       = o0;
                *(float2*)(Cf + (size_t)(row + 8) * N + col) = o1;
            }
        }
    }
}

// ===========================================================================
// Fused attention v5 (unchanged from R14): bias folded into QK mma.
// ===========================================================================
#define FST 68
__global__ void __launch_bounds__(256) attn_fused(
    const float* __restrict__ rs_ptr, float* __restrict__ attn)
{
    extern __shared__ uint32_t sm[];
    const uint32_t smb = (uint32_t)__cvta_generic_to_shared(sm);
    uint32_t* Vs = sm + 16384;
    float* pk_all = (float*)(sm + 25088);
    float* mred   = (float*)(sm + 27264);
    float* sred   = (float*)(sm + 27520);
    float* Mrow   = (float*)(sm + 27776);
    float* Irow   = (float*)(sm + 27904);

    const int tid = threadIdx.x, wid = tid >> 5, lane = tid & 31;
    const int gid = lane >> 2, tig = lane & 3;
    const int wy = wid >> 1, wx = wid & 1;
    const int bh = blockIdx.y, b = bh >> 4, h = bh & 15;
    const int tm = blockIdx.x * 128;
    const float rs = *rs_ptr;

    const int ar = tid >> 1, ah = tid & 1;

    const int mm = lane >> 3, rr = lane & 7;
    const int a_k  = mm >> 1, a_r8 = (mm & 1) * 8;
    const int b_k  = mm & 1,  b_n8 = (mm >> 1) * 8;
    uint32_t qa[2], kc[4], vc[4], qxa[2], kxo[4];
#pragma unroll
    for (int mi = 0; mi < 2; ++mi) {
        qa[mi]  = smb + (((wy * 32 + mi * 16 + a_r8 + rr) * 32) << 2);
        qxa[mi] = smb + ((28032 + (wy * 32 + mi * 16 + a_r8 + rr) * 8) << 2)
                  + (a_k << 4);
    }
#pragma unroll
    for (int np = 0; np < 4; ++np) {
        kc[np]  = (((wx * 64 + np * 16 + b_n8 + rr) * 32) << 2);
        vc[np]  = (((np * 16 + b_n8 + rr) * FST) << 2);
        kxo[np] = (((wx * 64 + np * 16 + b_n8 + rr) * 8) << 2) + (b_k << 4);
    }

#define ISSUE_Q() do {                                                       \
    const __half* _qg = g_qkvh + (size_t)(b * L_SZ + tm + ar) * E3_SZ        \
                        + h * 64 + ah * 32;                                  \
    uint32_t _qd = smb + ((ar * 32) << 2);                                   \
    _Pragma("unroll")                                                        \
    for (int cc = 0; cc < 4; ++cc) {                                         \
        int g = ah * 4 + cc;                                                 \
        cp16(_qd + (((g ^ (ar & 7)) << 2) << 2), _qg + cc * 8);              \
    }                                                                        \
} while (0)

#define ISSUE_K(j, s) do {                                                   \
    const __half* _kg = g_qkvh + (size_t)(b * L_SZ + (j) * 128 + ar) * E3_SZ \
                        + D_SZ + h * 64 + ah * 32;                           \
    uint32_t _kd = smb + ((4096 + (s) * 4096 + ar * 32) << 2);               \
    _Pragma("unroll")                                                        \
    for (int cc = 0; cc < 4; ++cc) {                                         \
        int g = ah * 4 + cc;                                                 \
        cp16(_kd + (((g ^ (ar & 7)) << 2) << 2), _kg + cc * 8);              \
    }                                                                        \
} while (0)

#define KX_FILL(j, s) do {                                                   \
    int _r = tid >> 1;                                                       \
    uint32_t* _kxp = sm + 29056 + (s) * 1024 + _r * 8;                       \
    if ((tid & 1) == 0) {                                                    \
        float _pk = pk_all[(j) * 128 + _r];                                  \
        uint4 _w = {f2h2(_pk, 1.0f), f2h2(rs * _pk * _pk, 0.f), 0u, 0u};     \
        *(uint4*)_kxp = _w;                                                  \
    } else {                                                                 \
        uint4 _z = {0u, 0u, 0u, 0u};                                         \
        *(uint4*)(_kxp + 4) = _z;                                            \
    }                                                                        \
} while (0)

#define LOAD_V(j, s) do {                                                    \
    int _kp = tid & 63, _dg = tid >> 6;                                      \
    const __half* _vp = g_qkvh + (size_t)(b * L_SZ + (j) * 128 + 2 * _kp)    \
                        * E3_SZ + 2 * D_SZ + h * 64 + _dg * 16;              \
    uint4 _r0 = *(const uint4*)_vp;                                          \
    uint4 _r1 = *(const uint4*)(_vp + E3_SZ);                                \
    uint4 _r2 = *(const uint4*)(_vp + 8);                                    \
    uint4 _r3 = *(const uint4*)(_vp + E3_SZ + 8);                            \
    uint32_t* _vd = Vs + (s) * 4352 + _kp;                                   \
    const unsigned short* _a0 = (const unsigned short*)&_r0;                 \
    const unsigned short* _a1 = (const unsigned short*)&_r1;                 \
    const unsigned short* _a2 = (const unsigned short*)&_r2;                 \
    const unsigned short* _a3 = (const unsigned short*)&_r3;                 \
    _Pragma("unroll")                                                        \
    for (int i = 0; i < 8; ++i) {                                            \
        _vd[(_dg * 16 + i) * FST]                                            \
            = (uint32_t)_a0[i] | ((uint32_t)_a1[i] << 16);                   \
        _vd[(_dg * 16 + 8 + i) * FST]                                        \
            = (uint32_t)_a2[i] | ((uint32_t)_a3[i] << 16);                   \
    }                                                                        \
} while (0)

#define QK_TILE(s) do {                                                      \
    _Pragma("unroll")                                                        \
    for (int i = 0; i < 2; ++i)                                              \
        _Pragma("unroll")                                                    \
        for (int n = 0; n < 8; ++n)                                          \
            _Pragma("unroll")                                                \
            for (int v = 0; v < 4; ++v) acc[i][n][v] = 0.f;                  \
    const uint32_t _kb  = smb + ((4096 + (s) * 4096) << 2);                  \
    const uint32_t _kxb = smb + ((29056 + (s) * 1024) << 2);                 \
    _Pragma("unroll")                                                        \
    for (int j4 = 0; j4 < 4; ++j4) {                                         \
        uint32_t a[2][4], bb[8][2];                                          \
        uint32_t _ax = (uint32_t)(((2 * j4 + a_k) ^ rr) << 4);               \
        uint32_t _bx = (uint32_t)(((2 * j4 + b_k) ^ rr) << 4);               \
        LDSM_X4(a[0][0], a[0][1], a[0][2], a[0][3], qa[0] + _ax);            \
        LDSM_X4(a[1][0], a[1][1], a[1][2], a[1][3], qa[1] + _ax);            \
        _Pragma("unroll")                                                    \
        for (int np = 0; np < 4; ++np)                                       \
            LDSM_X4(bb[2 * np][0], bb[2 * np][1],                            \
                    bb[2 * np + 1][0], bb[2 * np + 1][1],                    \
                    _kb + kc[np] + _bx);                                     \
        _Pragma("unroll")                                                    \
        for (int mi = 0; mi < 2; ++mi)                                       \
            _Pragma("unroll")                                                \
            for (int ni = 0; ni < 8; ++ni)                                   \
                mma_f16(acc[mi][ni], a[mi], bb[ni]);                         \
    }                                                                        \
    {                                                                        \
        uint32_t ae[2][4], be[8][2];                                         \
        LDSM_X4(ae[0][0], ae[0][1], ae[0][2], ae[0][3], qxa[0]);             \
        LDSM_X4(ae[1][0], ae[1][1], ae[1][2], ae[1][3], qxa[1]);             \
        _Pragma("unroll")                                                    \
        for (int np = 0; np < 4; ++np)                                       \
            LDSM_X4(be[2 * np][0], be[2 * np][1],                            \
                    be[2 * np + 1][0], be[2 * np + 1][1],                    \
                    _kxb + kxo[np]);                                         \
        _Pragma("unroll")                                                    \
        for (int mi = 0; mi < 2; ++mi)                                       \
            _Pragma("unroll")                                                \
            for (int ni = 0; ni < 8; ++ni)                                   \
                mma_f16(acc[mi][ni], ae[mi], be[ni]);                        \
    }                                                                        \
} while (0)

    float acc[2][8][4];

    // ===================== Pass A: stats only =====================
    float m_run[2][2], s_run[2][2];
#pragma unroll
    for (int i = 0; i < 2; ++i) {
        m_run[i][0] = NEG_INF; m_run[i][1] = NEG_INF;
        s_run[i][0] = 0.f;     s_run[i][1] = 0.f;
    }

    ISSUE_Q();
    ISSUE_K(0, 0);
    CP_COMMIT();
    ISSUE_K(1, 1);
    CP_COMMIT();
#pragma unroll
    for (int i = 0; i < 8; ++i)
        pk_all[tid + i * 256] = g_phase[(size_t)bh * L_SZ + tid + i * 256];
    if (tid < 128) {
        float pqv = g_phase[(size_t)bh * L_SZ + tm + tid];
        uint32_t* qxp = sm + 28032 + tid * 8;
        uint4 w = {f2h2(16.f * rs * pqv, -8.f * rs * pqv * pqv),
                   f2h2(-8.f, 0.f), 0u, 0u};
        *(uint4*)qxp = w;
        uint4 z = {0u, 0u, 0u, 0u};
        *(uint4*)(qxp + 4) = z;
    }
    __syncthreads();
    KX_FILL(0, 0);
    KX_FILL(1, 1);

    for (int j = 0; j < 16; ++j) {
        if (j < 15) { asm volatile("cp.async.wait_group 1;" ::: "memory"); }
        else        { asm volatile("cp.async.wait_group 0;" ::: "memory"); }
        __syncthreads();
        QK_TILE(j % 3);
#pragma unroll
        for (int mi = 0; mi < 2; ++mi) {
            float mx0 = NEG_INF, mx1 = NEG_INF;
#pragma unroll
            for (int ni = 0; ni < 8; ++ni) {
                mx0 = fmaxf(mx0, fmaxf(acc[mi][ni][0], acc[mi][ni][1]));
                mx1 = fmaxf(mx1, fmaxf(acc[mi][ni][2], acc[mi][ni][3]));
            }
            mx0 = fmaxf(mx0, __shfl_xor_sync(0xffffffff, mx0, 1));
            mx0 = fmaxf(mx0, __shfl_xor_sync(0xffffffff, mx0, 2));
            mx1 = fmaxf(mx1, __shfl_xor_sync(0xffffffff, mx1, 1));
            mx1 = fmaxf(mx1, __shfl_xor_sync(0xffffffff, mx1, 2));
            float h0 = EXPC * mx0, h1 = EXPC * mx1;
            float s0 = 0.f, s1 = 0.f;
#pragma unroll
            for (int ni = 0; ni < 8; ++ni) {
                s0 += exp2f(fmaf(EXPC, acc[mi][ni][0], -h0))
                    + exp2f(fmaf(EXPC, acc[mi][ni][1], -h0));
                s1 += exp2f(fmaf(EXPC, acc[mi][ni][2], -h1))
                    + exp2f(fmaf(EXPC, acc[mi][ni][3], -h1));
            }
            s0 += __shfl_xor_sync(0xffffffff, s0, 1);
            s0 += __shfl_xor_sync(0xffffffff, s0, 2);
            s1 += __shfl_xor_sync(0xffffffff, s1, 1);
            s1 += __shfl_xor_sync(0xffffffff, s1, 2);
            float mn0 = fmaxf(m_run[mi][0], mx0);
            s_run[mi][0] = s_run[mi][0] * exp2f(EXPC * (m_run[mi][0] - mn0))
                         + s0 * exp2f(EXPC * (mx0 - mn0));
            m_run[mi][0] = mn0;
            float mn1 = fmaxf(m_run[mi][1], mx1);
            s_run[mi][1] = s_run[mi][1] * exp2f(EXPC * (m_run[mi][1] - mn1))
                         + s1 * exp2f(EXPC * (mx1 - mn1));
            m_run[mi][1] = mn1;
        }
        if (j + 2 < 16) {
            ISSUE_K(j + 2, (j + 2) % 3);
            CP_COMMIT();
            KX_FILL(j + 2, (j + 2) % 3);
        }
    }

    if (tig == 0) {
#pragma unroll
        for (int mi = 0; mi < 2; ++mi) {
            int r0 = wy * 32 + mi * 16 + gid;
            mred[wx * 128 + r0]     = m_run[mi][0];
            sred[wx * 128 + r0]     = s_run[mi][0];
            mred[wx * 128 + r0 + 8] = m_run[mi][1];
            sred[wx * 128 + r0 + 8] = s_run[mi][1];
        }
    }
    __syncthreads();
    if (tid < 128) {
        float m0 = mred[tid], m1 = mred[128 + tid];
        float M = fmaxf(m0, m1);
        float S = sred[tid] * exp2f(EXPC * (m0 - M))
                + sred[128 + tid] * exp2f(EXPC * (m1 - M));
        Mrow[tid] = M;
        Irow[tid] = 1.0f / S;
    }
    __syncthreads();

    // ===================== Pass B: attn write + AV =====================
    float oacc[2][8][4];
#pragma unroll
    for (int i = 0; i < 2; ++i)
#pragma unroll
        for (int j = 0; j < 8; ++j)
#pragma unroll
            for (int v = 0; v < 4; ++v) oacc[i][j][v] = 0.f;

    float EMh[2][2], Ih[2][2];
#pragma unroll
    for (int mi = 0; mi < 2; ++mi) {
        int r0 = wy * 32 + mi * 16 + gid;
        EMh[mi][0] = EXPC * Mrow[r0];     Ih[mi][0] = Irow[r0];
        EMh[mi][1] = EXPC * Mrow[r0 + 8]; Ih[mi][1] = Irow[r0 + 8];
    }

    ISSUE_K(0, 0);
    CP_COMMIT();
    ISSUE_K(1, 1);
    CP_COMMIT();
    LOAD_V(0, 0);
    KX_FILL(0, 0);
    KX_FILL(1, 1);

    for (int j = 0; j < 16; ++j) {
        if (j < 15) { asm volatile("cp.async.wait_group 1;" ::: "memory"); }
        else        { asm volatile("cp.async.wait_group 0;" ::: "memory"); }
        __syncthreads();
        if (j + 1 < 16) LOAD_V(j + 1, (j + 1) & 1);
        QK_TILE(j % 3);

#pragma unroll
        for (int mi = 0; mi < 2; ++mi) {
            int r0 = wy * 32 + mi * 16 + gid;
            float EM0 = EMh[mi][0], I0 = Ih[mi][0];
            float EM1 = EMh[mi][1], I1 = Ih[mi][1];
            float* arow = attn + ((size_t)(bh * L_SZ + tm + r0)) * L_SZ + j * 128;
#pragma unroll
            for (int ni = 0; ni < 8; ++ni) {
                int c0f = wx * 64 + ni * 8 + tig * 2;
                float p00 = exp2f(fmaf(EXPC, acc[mi][ni][0], -EM0)) * I0;
                float p01 = exp2f(fmaf(EXPC, acc[mi][ni][1], -EM0)) * I0;
                float p10 = exp2f(fmaf(EXPC, acc[mi][ni][2], -EM1)) * I1;
                float p11 = exp2f(fmaf(EXPC, acc[mi][ni][3], -EM1)) * I1;
                acc[mi][ni][0] = p00; acc[mi][ni][1] = p01;
                acc[mi][ni][2] = p10; acc[mi][ni][3] = p11;
                *(float2*)(arow + c0f)            = make_float2(p00, p01);
                *(float2*)(arow + 8 * L_SZ + c0f) = make_float2(p10, p11);
            }
        }

        const uint32_t vb = smb + ((16384 + (j & 1) * 4352) << 2);
#pragma unroll
        for (int ss = 0; ss < 4; ++ss) {
            const int kw = wx * 32 + ss * 8;
            uint32_t a[2][4], bb[8][2];
#pragma unroll
            for (int mi = 0; mi < 2; ++mi) {
                a[mi][0] = f2h2(acc[mi][2 * ss][0],     acc[mi][2 * ss][1]);
                a[mi][1] = f2h2(acc[mi][2 * ss][2],     acc[mi][2 * ss][3]);
                a[mi][2] = f2h2(acc[mi][2 * ss + 1][0], acc[mi][2 * ss + 1][1]);
                a[mi][3] = f2h2(acc[mi][2 * ss + 1][2], acc[mi][2 * ss + 1][3]);
            }
            uint32_t vx = (uint32_t)((kw + 4 * b_k) << 2);
#pragma unroll
            for (int np = 0; np < 4; ++np)
                LDSM_X4(bb[2 * np][0], bb[2 * np][1],
                        bb[2 * np + 1][0], bb[2 * np + 1][1],
                        vb + vc[np] + vx);
#pragma unroll
            for (int mi = 0; mi < 2; ++mi)
#pragma unroll
                for (int ni2 = 0; ni2 < 8; ++ni2)
                    mma_f16(oacc[mi][ni2], a[mi], bb[ni2]);
        }
        if (j + 2 < 16) {
            ISSUE_K(j + 2, (j + 2) % 3);
            CP_COMMIT();
            KX_FILL(j + 2, (j + 2) % 3);
        }
    }
    __syncthreads();

    // O reduction across wx pairs, epilogue -> fp16 g_oh
    float* Ored = (float*)(sm + 4096);
    if (wx == 1) {
#pragma unroll
        for (int mi = 0; mi < 2; ++mi) {
            int rl = wy * 32 + mi * 16 + gid;
#pragma unroll
            for (int ni2 = 0; ni2 < 8; ++ni2) {
                int col = ni2 * 8 + tig * 2;
                Ored[rl * 65 + col]           = oacc[mi][ni2][0];
                Ored[rl * 65 + col + 1]       = oacc[mi][ni2][1];
                Ored[(rl + 8) * 65 + col]     = oacc[mi][ni2][2];
                Ored[(rl + 8) * 65 + col + 1] = oacc[mi][ni2][3];
            }
        }
    }
    __syncthreads();
    if (wx == 0) {
#pragma unroll
        for (int mi = 0; mi < 2; ++mi) {
            int rl = wy * 32 + mi * 16 + gid;
            int row = tm + rl;
#pragma unroll
            for (int ni2 = 0; ni2 < 8; ++ni2) {
                int col = ni2 * 8 + tig * 2;
                float s00 = oacc[mi][ni2][0] + Ored[rl * 65 + col];
                float s01 = oacc[mi][ni2][1] + Ored[rl * 65 + col + 1];
                float s10 = oacc[mi][ni2][2] + Ored[(rl + 8) * 65 + col];
                float s11 = oacc[mi][ni2][3] + Ored[(rl + 8) * 65 + col + 1];
                *(uint32_t*)(g_oh + (size_t)(b * L_SZ + row) * D_SZ + h * 64 + col)
                    = f2h2(s00, s01);
                *(uint32_t*)(g_oh + (size_t)(b * L_SZ + row + 8) * D_SZ + h * 64 + col)
                    = f2h2(s10, s11);
            }
        }
    }
}

// ---------------------------------------------------------------------------
// phase_val[bh, l] = tanh(ps * (x[b,l,:] . phase_w[h,:] + phase_b[h]))
// ---------------------------------------------------------------------------
__global__ __launch_bounds__(512) void phase_kernel(
    const float* __restrict__ x, const float* __restrict__ pw,
    const float* __restrict__ pb, const float* __restrict__ ps_ptr)
{
    const int bl = blockIdx.x;
    const int b  = bl >> 11;
    const int l  = bl & 2047;
    __shared__ float xs[1024];
    const int tid = threadIdx.x;
    for (int i = tid; i < 1024; i += 512) xs[i] = x[(size_t)bl * 1024 + i];
    __syncthreads();
    const int h = tid >> 5, lane = tid & 31;
    float s = 0.f;
    const float* w = pw + (size_t)h * 1024;
    for (int d = lane; d < 1024; d += 32) s += xs[d] * w[d];
#pragma unroll
    for (int o = 16; o; o >>= 1) s += __shfl_xor_sync(0xffffffff, s, o);
    if (lane == 0) {
        float ps = *ps_ptr;
        g_phase[(size_t)(b * H_SZ + h) * L_SZ + l] = tanhf(ps * (s + pb[h]));
    }
}

// ---------------------------------------------------------------------------
extern "C" void kernel_launch(void* const* d_in, const int* in_sizes, int n_in,
                              void* d_out, int out_size)
{
    const float* x      = (const float*)d_in[0];
    const float* qkv_w  = (const float*)d_in[1];
    const float* qkv_b  = (const float*)d_in[2];
    const float* out_w  = (const float*)d_in[3];
    const float* out_b  = (const float*)d_in[4];
    const float* ph_w   = (const float*)d_in[5];
    const float* ph_b   = (const float*)d_in[6];
    const float* rs_ptr = (const float*)d_in[7];
    const float* ps_ptr = (const float*)d_in[8];

    float* out_proj = (float*)d_out;                       // [2,2048,1024]
    float* attn     = out_proj + (size_t)MTOK * D_SZ;      // [2,16,2048,2048]

    __half *xh_ptr, *wqkvh_ptr, *wouth_ptr, *qkvh_ptr, *oh_ptr;
    cudaGetSymbolAddress((void**)&xh_ptr,    g_xh);
    cudaGetSymbolAddress((void**)&wqkvh_ptr, g_wqkvh);
    cudaGetSymbolAddress((void**)&wouth_ptr, g_wouth);
    cudaGetSymbolAddress((void**)&qkvh_ptr,  g_qkvh);
    cudaGetSymbolAddress((void**)&oh_ptr,    g_oh);

    const int SMEM_GEMM = 3 * 8192 * 4;     // 98304 -> 2 CTAs/SM
    const int SMEM_ATTN = 32128 * 4;        // 128512

    cudaFuncSetAttribute(gemm_mma<1>, cudaFuncAttributeMaxDynamicSharedMemorySize, SMEM_GEMM);
    cudaFuncSetAttribute(gemm_mma<0>, cudaFuncAttributeMaxDynamicSharedMemorySize, SMEM_GEMM);
    cudaFuncSetAttribute(attn_fused,  cudaFuncAttributeMaxDynamicSharedMemorySize, SMEM_ATTN);

    // 0) fp32 -> fp16 converts (x, qkv_w, out_w)
    f2h_kernel<<<(MTOK * D_SZ / 4 + 255) / 256, 256>>>(
        (const float4*)x, (uint2*)xh_ptr, MTOK * D_SZ / 4);
    f2h_kernel<<<(E3_SZ * D_SZ / 4 + 255) / 256, 256>>>(
        (const float4*)qkv_w, (uint2*)wqkvh_ptr, E3_SZ * D_SZ / 4);
    f2h_kernel<<<(D_SZ * D_SZ / 4 + 255) / 256, 256>>>(
        (const float4*)out_w, (uint2*)wouth_ptr, D_SZ * D_SZ / 4);

    // 1) fused QKV projection -> fp16 qkv
    gemm_mma<1><<<dim3(E3_SZ / 128, MTOK / 128), 256, SMEM_GEMM>>>(
        xh_ptr, wqkvh_ptr, qkv_b, qkvh_ptr, E3_SZ, D_SZ);

    // 2) per-head phase values
    phase_kernel<<<MTOK, 512>>>(x, ph_w, ph_b, ps_ptr);

    // 3) fused scores + softmax + attn write + AV (bias folded into mma)
    attn_fused<<<dim3(L_SZ / 128, BH_SZ), 256, SMEM_ATTN>>>(rs_ptr, attn);

    // 4) output projection (fp32 out)
    gemm_mma<0><<<dim3(D_SZ / 128, MTOK / 128), 256, SMEM_GEMM>>>(
        oh_ptr, wouth_ptr, out_b, out_proj, D_SZ, D_SZ);
}

// round 16
// speedup vs baseline: 1.0184x; 1.0184x over previous
#include <cuda_runtime.h>
#include <cuda_fp16.h>
#include <math.h>
#include <stdint.h>

// Problem constants
#define B_SZ   2
#define L_SZ   2048
#define D_SZ   1024
#define H_SZ   16
#define E3_SZ  3072
#define MTOK   (B_SZ * L_SZ)        // 4096
#define BH_SZ  32

#define NEG_INF __int_as_float(0xff800000)
#define EXPC 0.18033688f            // 0.125 * log2(e)

// Scratch (device globals; allocation is forbidden)
__device__ __half g_xh[(size_t)MTOK * D_SZ];          // fp16 x
__device__ __half g_wqkvh[(size_t)E3_SZ * D_SZ];      // fp16 qkv_w
__device__ __half g_wouth[(size_t)D_SZ * D_SZ];       // fp16 out_w
__device__ __half g_qkvh[(size_t)MTOK * E3_SZ];       // fp16 qkv
__device__ __half g_oh[(size_t)MTOK * D_SZ];          // fp16 O (pre out-proj)
__device__ float  g_phase[(size_t)BH_SZ * L_SZ];      // [bh, l]

// ---------------------------------------------------------------------------
// helpers
// ---------------------------------------------------------------------------
__device__ __forceinline__ uint32_t f2h2(float lo, float hi) {
    __half2 h = __floats2half2_rn(lo, hi);
    return *reinterpret_cast<uint32_t*>(&h);
}
__device__ __forceinline__ void mma_f16(float c[4], const uint32_t a[4],
                                        const uint32_t b[2]) {
    asm volatile(
        "mma.sync.aligned.m16n8k16.row.col.f32.f16.f16.f32 "
        "{%0,%1,%2,%3}, {%4,%5,%6,%7}, {%8,%9}, {%0,%1,%2,%3};"
        : "+f"(c[0]), "+f"(c[1]), "+f"(c[2]), "+f"(c[3])
        : "r"(a[0]), "r"(a[1]), "r"(a[2]), "r"(a[3]), "r"(b[0]), "r"(b[1]));
}
__device__ __forceinline__ void cp16(uint32_t dst, const void* src) {
    asm volatile("cp.async.cg.shared.global [%0], [%1], 16;"
                 :: "r"(dst), "l"(src) : "memory");
}
#define CP_COMMIT() asm volatile("cp.async.commit_group;" ::: "memory")

#define LDSM_X4(r0, r1, r2, r3, addr)                                        \
    asm volatile("ldmatrix.sync.aligned.m8n8.x4.shared.b16 "                 \
                 "{%0,%1,%2,%3}, [%4];"                                      \
                 : "=r"(r0), "=r"(r1), "=r"(r2), "=r"(r3) : "r"(addr))

// ---------------------------------------------------------------------------
// fp32 -> fp16 elementwise convert (vectorized x4)
// ---------------------------------------------------------------------------
__global__ void __launch_bounds__(256) f2h_kernel(
    const float4* __restrict__ src, uint2* __restrict__ dst, int n4)
{
    int i = blockIdx.x * 256 + threadIdx.x;
    if (i < n4) {
        float4 v = src[i];
        uint2 o = {f2h2(v.x, v.y), f2h2(v.z, v.w)};
        dst[i] = o;
    }
}

// ===========================================================================
// GEMM (R12/R14 exact): C = A @ B^T + bias, all-fp16 in, fp32 acc.
// CTA 128x256, 8 warps (2x4), warp tile 64x64, 3-stage cp.async ring,
// ldmatrix fragments.
// ===========================================================================
template<int OUTH>
__global__ void __launch_bounds__(256) gemm_mma(
    const __half* __restrict__ A, const __half* __restrict__ Bm,
    const float* __restrict__ bias, void* __restrict__ Cv, int N, int K)
{
    extern __shared__ uint32_t sm[];
    const uint32_t smb = (uint32_t)__cvta_generic_to_shared(sm);
    const int tid = threadIdx.x, wid = tid >> 5, lane = tid & 31;
    const int gid = lane >> 2, tig = lane & 3;
    const int wy = wid >> 2, wx = wid & 3;
    const int tm = blockIdx.y * 128, tn = blockIdx.x * 256;

    const int ar = tid >> 1, ah = tid & 1;
    const __half* ag = A  + (size_t)(tm + ar)  * K + ah * 32;
    const __half* bg = Bm + (size_t)(tn + tid) * K;

    const int mm = lane >> 3, rr = lane & 7;
    const int a_k = mm >> 1, a_r8 = (mm & 1) * 8;
    const int b_k = mm & 1,  b_n8 = (mm >> 1) * 8;
    uint32_t aoff[4], boff[4];
#pragma unroll
    for (int mi = 0; mi < 4; ++mi)
        aoff[mi] = (uint32_t)(((wy * 64 + mi * 16 + a_r8 + rr) * 32) << 2);
#pragma unroll
    for (int np = 0; np < 4; ++np)
        boff[np] = (uint32_t)(((4096 + (wx * 64 + np * 16 + b_n8 + rr) * 32)) << 2);

    float acc[4][8][4];
#pragma unroll
    for (int i = 0; i < 4; ++i)
#pragma unroll
        for (int j = 0; j < 8; ++j)
#pragma unroll
            for (int v = 0; v < 4; ++v) acc[i][j][v] = 0.f;

    const int T = K >> 6;

#define G_ISSUE(t, s) do {                                                   \
    const __half* _ap = ag + (t) * 64;                                       \
    const __half* _bp = bg + (t) * 64;                                       \
    uint32_t _ad = smb + (((s) * 12288 + ar * 32) << 2);                     \
    uint32_t _bd = smb + (((s) * 12288 + 4096 + tid * 32) << 2);             \
    _Pragma("unroll")                                                        \
    for (int cc = 0; cc < 4; ++cc) {                                         \
        int g = ah * 4 + cc;                                                 \
        cp16(_ad + (((g ^ (ar & 7)) << 2) << 2), _ap + cc * 8);              \
    }                                                                        \
    _Pragma("unroll")                                                        \
    for (int cc = 0; cc < 8; ++cc)                                           \
        cp16(_bd + (((cc ^ (tid & 7)) << 2) << 2), _bp + cc * 8);            \
} while (0)

    G_ISSUE(0, 0);
    CP_COMMIT();
    if (T > 1) { G_ISSUE(1, 1); CP_COMMIT(); }

    for (int t = 0; t < T; ++t) {
        if (t + 1 < T) { asm volatile("cp.async.wait_group 1;" ::: "memory"); }
        else           { asm volatile("cp.async.wait_group 0;" ::: "memory"); }
        __syncthreads();
        const uint32_t sbase = smb + (((t % 3) * 12288) << 2);
#pragma unroll
        for (int j4 = 0; j4 < 4; ++j4) {
            uint32_t ax = (uint32_t)(((2 * j4 + a_k) ^ rr) << 4);
            uint32_t bx = (uint32_t)(((2 * j4 + b_k) ^ rr) << 4);
            uint32_t a[4][4], b2[8][2];
#pragma unroll
            for (int mi = 0; mi < 4; ++mi)
                LDSM_X4(a[mi][0], a[mi][1], a[mi][2], a[mi][3],
                        sbase + aoff[mi] + ax);
#pragma unroll
            for (int np = 0; np < 4; ++np)
                LDSM_X4(b2[2 * np][0], b2[2 * np][1],
                        b2[2 * np + 1][0], b2[2 * np + 1][1],
                        sbase + boff[np] + bx);
#pragma unroll
            for (int mi = 0; mi < 4; ++mi)
#pragma unroll
                for (int ni = 0; ni < 8; ++ni)
                    mma_f16(acc[mi][ni], a[mi], b2[ni]);
        }
        __syncthreads();
        if (t + 2 < T) { G_ISSUE(t + 2, (t + 2) % 3); CP_COMMIT(); }
    }

#pragma unroll
    for (int mi = 0; mi < 4; ++mi) {
        int row = tm + wy * 64 + mi * 16 + gid;
#pragma unroll
        for (int ni = 0; ni < 8; ++ni) {
            int col = tn + wx * 64 + ni * 8 + tig * 2;
            float b0 = bias[col], b1 = bias[col + 1];
            if (OUTH) {
                __half* Ch = (__half*)Cv;
                *(uint32_t*)(Ch + (size_t)row * N + col) =
                    f2h2(acc[mi][ni][0] + b0, acc[mi][ni][1] + b1);
                *(uint32_t*)(Ch + (size_t)(row + 8) * N + col) =
                    f2h2(acc[mi][ni][2] + b0, acc[mi][ni][3] + b1);
            } else {
                float* Cf = (float*)Cv;
                float2 o0 = {acc[mi][ni][0] + b0, acc[mi][ni][1] + b1};
                float2 o1 = {acc[mi][ni][2] + b0, acc[mi][ni][3] + b1};
                *(float2*)(Cf + (size_t)row * N + col)       = o0;
                *(float2*)(Cf + (size_t)(row + 8) * N + col) = o1;
            }
        }
    }
}

// ===========================================================================
// Fused attention v5 (R14 exact): bias folded into QK mma.
// ===========================================================================
#define FST 68
__global__ void __launch_bounds__(256) attn_fused(
    const float* __restrict__ rs_ptr, float* __restrict__ attn)
{
    extern __shared__ uint32_t sm[];
    const uint32_t smb = (uint32_t)__cvta_generic_to_shared(sm);
    uint32_t* Vs = sm + 16384;
    float* pk_all = (float*)(sm + 25088);
    float* mred   = (float*)(sm + 27264);
    float* sred   = (float*)(sm + 27520);
    float* Mrow   = (float*)(sm + 27776);
    float* Irow   = (float*)(sm + 27904);

    const int tid = threadIdx.x, wid = tid >> 5, lane = tid & 31;
    const int gid = lane >> 2, tig = lane & 3;
    const int wy = wid >> 1, wx = wid & 1;
    const int bh = blockIdx.y, b = bh >> 4, h = bh & 15;
    const int tm = blockIdx.x * 128;
    const float rs = *rs_ptr;

    const int ar = tid >> 1, ah = tid & 1;

    const int mm = lane >> 3, rr = lane & 7;
    const int a_k  = mm >> 1, a_r8 = (mm & 1) * 8;
    const int b_k  = mm & 1,  b_n8 = (mm >> 1) * 8;
    uint32_t qa[2], kc[4], vc[4], qxa[2], kxo[4];
#pragma unroll
    for (int mi = 0; mi < 2; ++mi) {
        qa[mi]  = smb + (((wy * 32 + mi * 16 + a_r8 + rr) * 32) << 2);
        qxa[mi] = smb + ((28032 + (wy * 32 + mi * 16 + a_r8 + rr) * 8) << 2)
                  + (a_k << 4);
    }
#pragma unroll
    for (int np = 0; np < 4; ++np) {
        kc[np]  = (((wx * 64 + np * 16 + b_n8 + rr) * 32) << 2);
        vc[np]  = (((np * 16 + b_n8 + rr) * FST) << 2);
        kxo[np] = (((wx * 64 + np * 16 + b_n8 + rr) * 8) << 2) + (b_k << 4);
    }

#define ISSUE_Q() do {                                                       \
    const __half* _qg = g_qkvh + (size_t)(b * L_SZ + tm + ar) * E3_SZ        \
                        + h * 64 + ah * 32;                                  \
    uint32_t _qd = smb + ((ar * 32) << 2);                                   \
    _Pragma("unroll")                                                        \
    for (int cc = 0; cc < 4; ++cc) {                                         \
        int g = ah * 4 + cc;                                                 \
        cp16(_qd + (((g ^ (ar & 7)) << 2) << 2), _qg + cc * 8);              \
    }                                                                        \
} while (0)

#define ISSUE_K(j, s) do {                                                   \
    const __half* _kg = g_qkvh + (size_t)(b * L_SZ + (j) * 128 + ar) * E3_SZ \
                        + D_SZ + h * 64 + ah * 32;                           \
    uint32_t _kd = smb + ((4096 + (s) * 4096 + ar * 32) << 2);               \
    _Pragma("unroll")                                                        \
    for (int cc = 0; cc < 4; ++cc) {                                         \
        int g = ah * 4 + cc;                                                 \
        cp16(_kd + (((g ^ (ar & 7)) << 2) << 2), _kg + cc * 8);              \
    }                                                                        \
} while (0)

#define KX_FILL(j, s) do {                                                   \
    int _r = tid >> 1;                                                       \
    uint32_t* _kxp = sm + 29056 + (s) * 1024 + _r * 8;                       \
    if ((tid & 1) == 0) {                                                    \
        float _pk = pk_all[(j) * 128 + _r];                                  \
        uint4 _w = {f2h2(_pk, 1.0f), f2h2(rs * _pk * _pk, 0.f), 0u, 0u};     \
        *(uint4*)_kxp = _w;                                                  \
    } else {                                                                 \
        uint4 _z = {0u, 0u, 0u, 0u};                                         \
        *(uint4*)(_kxp + 4) = _z;                                            \
    }                                                                        \
} while (0)

#define LOAD_V(j, s) do {                                                    \
    int _kp = tid & 63, _dg = tid >> 6;                                      \
    const __half* _vp = g_qkvh + (size_t)(b * L_SZ + (j) * 128 + 2 * _kp)    \
                        * E3_SZ + 2 * D_SZ + h * 64 + _dg * 16;              \
    uint4 _r0 = *(const uint4*)_vp;                                          \
    uint4 _r1 = *(const uint4*)(_vp + E3_SZ);                                \
    uint4 _r2 = *(const uint4*)(_vp + 8);                                    \
    uint4 _r3 = *(const uint4*)(_vp + E3_SZ + 8);                            \
    uint32_t* _vd = Vs + (s) * 4352 + _kp;                                   \
    const unsigned short* _a0 = (const unsigned short*)&_r0;                 \
    const unsigned short* _a1 = (const unsigned short*)&_r1;                 \
    const unsigned short* _a2 = (const unsigned short*)&_r2;                 \
    const unsigned short* _a3 = (const unsigned short*)&_r3;                 \
    _Pragma("unroll")                                                        \
    for (int i = 0; i < 8; ++i) {                                            \
        _vd[(_dg * 16 + i) * FST]                                            \
            = (uint32_t)_a0[i] | ((uint32_t)_a1[i] << 16);                   \
        _vd[(_dg * 16 + 8 + i) * FST]                                        \
            = (uint32_t)_a2[i] | ((uint32_t)_a3[i] << 16);                   \
    }                                                                        \
} while (0)

#define QK_TILE(s) do {                                                      \
    _Pragma("unroll")                                                        \
    for (int i = 0; i < 2; ++i)                                              \
        _Pragma("unroll")                                                    \
        for (int n = 0; n < 8; ++n)                                          \
            _Pragma("unroll")                                                \
            for (int v = 0; v < 4; ++v) acc[i][n][v] = 0.f;                  \
    const uint32_t _kb  = smb + ((4096 + (s) * 4096) << 2);                  \
    const uint32_t _kxb = smb + ((29056 + (s) * 1024) << 2);                 \
    _Pragma("unroll")                                                        \
    for (int j4 = 0; j4 < 4; ++j4) {                                         \
        uint32_t a[2][4], bb[8][2];                                          \
        uint32_t _ax = (uint32_t)(((2 * j4 + a_k) ^ rr) << 4);               \
        uint32_t _bx = (uint32_t)(((2 * j4 + b_k) ^ rr) << 4);               \
        LDSM_X4(a[0][0], a[0][1], a[0][2], a[0][3], qa[0] + _ax);            \
        LDSM_X4(a[1][0], a[1][1], a[1][2], a[1][3], qa[1] + _ax);            \
        _Pragma("unroll")                                                    \
        for (int np = 0; np < 4; ++np)                                       \
            LDSM_X4(bb[2 * np][0], bb[2 * np][1],                            \
                    bb[2 * np + 1][0], bb[2 * np + 1][1],                    \
                    _kb + kc[np] + _bx);                                     \
        _Pragma("unroll")                                                    \
        for (int mi = 0; mi < 2; ++mi)                                       \
            _Pragma("unroll")                                                \
            for (int ni = 0; ni < 8; ++ni)                                   \
                mma_f16(acc[mi][ni], a[mi], bb[ni]);                         \
    }                                                                        \
    {                                                                        \
        uint32_t ae[2][4], be[8][2];                                         \
        LDSM_X4(ae[0][0], ae[0][1], ae[0][2], ae[0][3], qxa[0]);             \
        LDSM_X4(ae[1][0], ae[1][1], ae[1][2], ae[1][3], qxa[1]);             \
        _Pragma("unroll")                                                    \
        for (int np = 0; np < 4; ++np)                                       \
            LDSM_X4(be[2 * np][0], be[2 * np][1],                            \
                    be[2 * np + 1][0], be[2 * np + 1][1],                    \
                    _kxb + kxo[np]);                                         \
        _Pragma("unroll")                                                    \
        for (int mi = 0; mi < 2; ++mi)                                       \
            _Pragma("unroll")                                                \
            for (int ni = 0; ni < 8; ++ni)                                   \
                mma_f16(acc[mi][ni], ae[mi], be[ni]);                        \
    }                                                                        \
} while (0)

    float acc[2][8][4];

    // ===================== Pass A: stats only =====================
    float m_run[2][2], s_run[2][2];
#pragma unroll
    for (int i = 0; i < 2; ++i) {
        m_run[i][0] = NEG_INF; m_run[i][1] = NEG_INF;
        s_run[i][0] = 0.f;     s_run[i][1] = 0.f;
    }

    ISSUE_Q();
    ISSUE_K(0, 0);
    CP_COMMIT();
    ISSUE_K(1, 1);
    CP_COMMIT();
#pragma unroll
    for (int i = 0; i < 8; ++i)
        pk_all[tid + i * 256] = g_phase[(size_t)bh * L_SZ + tid + i * 256];
    if (tid < 128) {
        float pqv = g_phase[(size_t)bh * L_SZ + tm + tid];
        uint32_t* qxp = sm + 28032 + tid * 8;
        uint4 w = {f2h2(16.f * rs * pqv, -8.f * rs * pqv * pqv),
                   f2h2(-8.f, 0.f), 0u, 0u};
        *(uint4*)qxp = w;
        uint4 z = {0u, 0u, 0u, 0u};
        *(uint4*)(qxp + 4) = z;
    }
    __syncthreads();
    KX_FILL(0, 0);
    KX_FILL(1, 1);

    for (int j = 0; j < 16; ++j) {
        if (j < 15) { asm volatile("cp.async.wait_group 1;" ::: "memory"); }
        else        { asm volatile("cp.async.wait_group 0;" ::: "memory"); }
        __syncthreads();
        QK_TILE(j % 3);
#pragma unroll
        for (int mi = 0; mi < 2; ++mi) {
            float mx0 = NEG_INF, mx1 = NEG_INF;
#pragma unroll
            for (int ni = 0; ni < 8; ++ni) {
                mx0 = fmaxf(mx0, fmaxf(acc[mi][ni][0], acc[mi][ni][1]));
                mx1 = fmaxf(mx1, fmaxf(acc[mi][ni][2], acc[mi][ni][3]));
            }
            mx0 = fmaxf(mx0, __shfl_xor_sync(0xffffffff, mx0, 1));
            mx0 = fmaxf(mx0, __shfl_xor_sync(0xffffffff, mx0, 2));
            mx1 = fmaxf(mx1, __shfl_xor_sync(0xffffffff, mx1, 1));
            mx1 = fmaxf(mx1, __shfl_xor_sync(0xffffffff, mx1, 2));
            float h0 = EXPC * mx0, h1 = EXPC * mx1;
            float s0 = 0.f, s1 = 0.f;
#pragma unroll
            for (int ni = 0; ni < 8; ++ni) {
                s0 += exp2f(fmaf(EXPC, acc[mi][ni][0], -h0))
                    + exp2f(fmaf(EXPC, acc[mi][ni][1], -h0));
                s1 += exp2f(fmaf(EXPC, acc[mi][ni][2], -h1))
                    + exp2f(fmaf(EXPC, acc[mi][ni][3], -h1));
            }
            s0 += __shfl_xor_sync(0xffffffff, s0, 1);
            s0 += __shfl_xor_sync(0xffffffff, s0, 2);
            s1 += __shfl_xor_sync(0xffffffff, s1, 1);
            s1 += __shfl_xor_sync(0xffffffff, s1, 2);
            float mn0 = fmaxf(m_run[mi][0], mx0);
            s_run[mi][0] = s_run[mi][0] * exp2f(EXPC * (m_run[mi][0] - mn0))
                         + s0 * exp2f(EXPC * (mx0 - mn0));
            m_run[mi][0] = mn0;
            float mn1 = fmaxf(m_run[mi][1], mx1);
            s_run[mi][1] = s_run[mi][1] * exp2f(EXPC * (m_run[mi][1] - mn1))
                         + s1 * exp2f(EXPC * (mx1 - mn1));
            m_run[mi][1] = mn1;
        }
        if (j + 2 < 16) {
            ISSUE_K(j + 2, (j + 2) % 3);
            CP_COMMIT();
            KX_FILL(j + 2, (j + 2) % 3);
        }
    }

    if (tig == 0) {
#pragma unroll
        for (int mi = 0; mi < 2; ++mi) {
            int r0 = wy * 32 + mi * 16 + gid;
            mred[wx * 128 + r0]     = m_run[mi][0];
            sred[wx * 128 + r0]     = s_run[mi][0];
            mred[wx * 128 + r0 + 8] = m_run[mi][1];
            sred[wx * 128 + r0 + 8] = s_run[mi][1];
        }
    }
    __syncthreads();
    if (tid < 128) {
        float m0 = mred[tid], m1 = mred[128 + tid];
        float M = fmaxf(m0, m1);
        float S = sred[tid] * exp2f(EXPC * (m0 - M))
                + sred[128 + tid] * exp2f(EXPC * (m1 - M));
        Mrow[tid] = M;
        Irow[tid] = 1.0f / S;
    }
    __syncthreads();

    // ===================== Pass B: attn write + AV =====================
    float oacc[2][8][4];
#pragma unroll
    for (int i = 0; i < 2; ++i)
#pragma unroll
        for (int j = 0; j < 8; ++j)
#pragma unroll
            for (int v = 0; v < 4; ++v) oacc[i][j][v] = 0.f;

    float EMh[2][2], Ih[2][2];
#pragma unroll
    for (int mi = 0; mi < 2; ++mi) {
        int r0 = wy * 32 + mi * 16 + gid;
        EMh[mi][0] = EXPC * Mrow[r0];     Ih[mi][0] = Irow[r0];
        EMh[mi][1] = EXPC * Mrow[r0 + 8]; Ih[mi][1] = Irow[r0 + 8];
    }

    ISSUE_K(0, 0);
    CP_COMMIT();
    ISSUE_K(1, 1);
    CP_COMMIT();
    LOAD_V(0, 0);
    KX_FILL(0, 0);
    KX_FILL(1, 1);

    for (int j = 0; j < 16; ++j) {
        if (j < 15) { asm volatile("cp.async.wait_group 1;" ::: "memory"); }
        else        { asm volatile("cp.async.wait_group 0;" ::: "memory"); }
        __syncthreads();
        if (j + 1 < 16) LOAD_V(j + 1, (j + 1) & 1);
        QK_TILE(j % 3);

#pragma unroll
        for (int mi = 0; mi < 2; ++mi) {
            int r0 = wy * 32 + mi * 16 + gid;
            float EM0 = EMh[mi][0], I0 = Ih[mi][0];
            float EM1 = EMh[mi][1], I1 = Ih[mi][1];
            float* arow = attn + ((size_t)(bh * L_SZ + tm + r0)) * L_SZ + j * 128;
#pragma unroll
            for (int ni = 0; ni < 8; ++ni) {
                int c0f = wx * 64 + ni * 8 + tig * 2;
                float p00 = exp2f(fmaf(EXPC, acc[mi][ni][0], -EM0)) * I0;
                float p01 = exp2f(fmaf(EXPC, acc[mi][ni][1], -EM0)) * I0;
                float p10 = exp2f(fmaf(EXPC, acc[mi][ni][2], -EM1)) * I1;
                float p11 = exp2f(fmaf(EXPC, acc[mi][ni][3], -EM1)) * I1;
                acc[mi][ni][0] = p00; acc[mi][ni][1] = p01;
                acc[mi][ni][2] = p10; acc[mi][ni][3] = p11;
                *(float2*)(arow + c0f)            = make_float2(p00, p01);
                *(float2*)(arow + 8 * L_SZ + c0f) = make_float2(p10, p11);
            }
        }

        const uint32_t vb = smb + ((16384 + (j & 1) * 4352) << 2);
#pragma unroll
        for (int ss = 0; ss < 4; ++ss) {
            const int kw = wx * 32 + ss * 8;
            uint32_t a[2][4], bb[8][2];
#pragma unroll
            for (int mi = 0; mi < 2; ++mi) {
                a[mi][0] = f2h2(acc[mi][2 * ss][0],     acc[mi][2 * ss][1]);
                a[mi][1] = f2h2(acc[mi][2 * ss][2],     acc[mi][2 * ss][3]);
                a[mi][2] = f2h2(acc[mi][2 * ss + 1][0], acc[mi][2 * ss + 1][1]);
                a[mi][3] = f2h2(acc[mi][2 * ss + 1][2], acc[mi][2 * ss + 1][3]);
            }
            uint32_t vx = (uint32_t)((kw + 4 * b_k) << 2);
#pragma unroll
            for (int np = 0; np < 4; ++np)
                LDSM_X4(bb[2 * np][0], bb[2 * np][1],
                        bb[2 * np + 1][0], bb[2 * np + 1][1],
                        vb + vc[np] + vx);
#pragma unroll
            for (int mi = 0; mi < 2; ++mi)
#pragma unroll
                for (int ni2 = 0; ni2 < 8; ++ni2)
                    mma_f16(oacc[mi][ni2], a[mi], bb[ni2]);
        }
        if (j + 2 < 16) {
            ISSUE_K(j + 2, (j + 2) % 3);
            CP_COMMIT();
            KX_FILL(j + 2, (j + 2) % 3);
        }
    }
    __syncthreads();

    // O reduction across wx pairs, epilogue -> fp16 g_oh
    float* Ored = (float*)(sm + 4096);
    if (wx == 1) {
#pragma unroll
        for (int mi = 0; mi < 2; ++mi) {
            int rl = wy * 32 + mi * 16 + gid;
#pragma unroll
            for (int ni2 = 0; ni2 < 8; ++ni2) {
                int col = ni2 * 8 + tig * 2;
                Ored[rl * 65 + col]           = oacc[mi][ni2][0];
                Ored[rl * 65 + col + 1]       = oacc[mi][ni2][1];
                Ored[(rl + 8) * 65 + col]     = oacc[mi][ni2][2];
                Ored[(rl + 8) * 65 + col + 1] = oacc[mi][ni2][3];
            }
        }
    }
    __syncthreads();
    if (wx == 0) {
#pragma unroll
        for (int mi = 0; mi < 2; ++mi) {
            int rl = wy * 32 + mi * 16 + gid;
            int row = tm + rl;
#pragma unroll
            for (int ni2 = 0; ni2 < 8; ++ni2) {
                int col = ni2 * 8 + tig * 2;
                float s00 = oacc[mi][ni2][0] + Ored[rl * 65 + col];
                float s01 = oacc[mi][ni2][1] + Ored[rl * 65 + col + 1];
                float s10 = oacc[mi][ni2][2] + Ored[(rl + 8) * 65 + col];
                float s11 = oacc[mi][ni2][3] + Ored[(rl + 8) * 65 + col + 1];
                *(uint32_t*)(g_oh + (size_t)(b * L_SZ + row) * D_SZ + h * 64 + col)
                    = f2h2(s00, s01);
                *(uint32_t*)(g_oh + (size_t)(b * L_SZ + row + 8) * D_SZ + h * 64 + col)
                    = f2h2(s10, s11);
            }
        }
    }
}

// ---------------------------------------------------------------------------
// phase_val + fused x fp32->fp16 convert.
// phase_val[bh, l] = tanh(ps * (x[b,l,:] . phase_w[h,:] + phase_b[h]))
// Also writes g_xh[bl, :] = fp16(x[bl, :]) (x row already staged in SMEM).
// ---------------------------------------------------------------------------
__global__ __launch_bounds__(512) void phase_kernel(
    const float* __restrict__ x, const float* __restrict__ pw,
    const float* __restrict__ pb, const float* __restrict__ ps_ptr)
{
    const int bl = blockIdx.x;
    const int b  = bl >> 11;
    const int l  = bl & 2047;
    __shared__ float xs[1024];
    const int tid = threadIdx.x;
    for (int i = tid; i < 1024; i += 512) xs[i] = x[(size_t)bl * 1024 + i];
    __syncthreads();

    // fused convert: two halves2 per thread
    {
        float2 v = *(const float2*)(xs + tid * 2);
        *(uint32_t*)(g_xh + (size_t)bl * 1024 + tid * 2) = f2h2(v.x, v.y);
    }

    const int h = tid >> 5, lane = tid & 31;
    float s = 0.f;
    const float* w = pw + (size_t)h * 1024;
    for (int d = lane; d < 1024; d += 32) s += xs[d] * w[d];
#pragma unroll
    for (int o = 16; o; o >>= 1) s += __shfl_xor_sync(0xffffffff, s, o);
    if (lane == 0) {
        float ps = *ps_ptr;
        g_phase[(size_t)(b * H_SZ + h) * L_SZ + l] = tanhf(ps * (s + pb[h]));
    }
}

// ---------------------------------------------------------------------------
extern "C" void kernel_launch(void* const* d_in, const int* in_sizes, int n_in,
                              void* d_out, int out_size)
{
    const float* x      = (const float*)d_in[0];
    const float* qkv_w  = (const float*)d_in[1];
    const float* qkv_b  = (const float*)d_in[2];
    const float* out_w  = (const float*)d_in[3];
    const float* out_b  = (const float*)d_in[4];
    const float* ph_w   = (const float*)d_in[5];
    const float* ph_b   = (const float*)d_in[6];
    const float* rs_ptr = (const float*)d_in[7];
    const float* ps_ptr = (const float*)d_in[8];

    float* out_proj = (float*)d_out;                       // [2,2048,1024]
    float* attn     = out_proj + (size_t)MTOK * D_SZ;      // [2,16,2048,2048]

    __half *xh_ptr, *wqkvh_ptr, *wouth_ptr, *qkvh_ptr, *oh_ptr;
    cudaGetSymbolAddress((void**)&xh_ptr,    g_xh);
    cudaGetSymbolAddress((void**)&wqkvh_ptr, g_wqkvh);
    cudaGetSymbolAddress((void**)&wouth_ptr, g_wouth);
    cudaGetSymbolAddress((void**)&qkvh_ptr,  g_qkvh);
    cudaGetSymbolAddress((void**)&oh_ptr,    g_oh);

    const int SMEM_GEMM = 3 * 12288 * 4;    // 147456
    const int SMEM_ATTN = 32128 * 4;        // 128512

    cudaFuncSetAttribute(gemm_mma<1>, cudaFuncAttributeMaxDynamicSharedMemorySize, SMEM_GEMM);
    cudaFuncSetAttribute(gemm_mma<0>, cudaFuncAttributeMaxDynamicSharedMemorySize, SMEM_GEMM);
    cudaFuncSetAttribute(attn_fused,  cudaFuncAttributeMaxDynamicSharedMemorySize, SMEM_ATTN);

    // 0) weight converts (x convert fused into phase_kernel)
    f2h_kernel<<<(E3_SZ * D_SZ / 4 + 255) / 256, 256>>>(
        (const float4*)qkv_w, (uint2*)wqkvh_ptr, E3_SZ * D_SZ / 4);
    f2h_kernel<<<(D_SZ * D_SZ / 4 + 255) / 256, 256>>>(
        (const float4*)out_w, (uint2*)wouth_ptr, D_SZ * D_SZ / 4);

    // 1) per-head phase values + x -> fp16 (must precede QKV gemm)
    phase_kernel<<<MTOK, 512>>>(x, ph_w, ph_b, ps_ptr);

    // 2) fused QKV projection -> fp16 qkv
    gemm_mma<1><<<dim3(E3_SZ / 256, MTOK / 128), 256, SMEM_GEMM>>>(
        xh_ptr, wqkvh_ptr, qkv_b, qkvh_ptr, E3_SZ, D_SZ);

    // 3) fused scores + softmax + attn write + AV (bias folded into mma)
    attn_fused<<<dim3(L_SZ / 128, BH_SZ), 256, SMEM_ATTN>>>(rs_ptr, attn);

    // 4) output projection (fp32 out)
    gemm_mma<0><<<dim3(D_SZ / 256, MTOK / 128), 256, SMEM_GEMM>>>(
        oh_ptr, wouth_ptr, out_b, out_proj, D_SZ, D_SZ);
}